// round 1
// baseline (speedup 1.0000x reference)
#include <cuda_runtime.h>
#include <cstddef>

// RFFT2d: x (32,1,1024,1024) fp32 -> per 8x8 block, 8-point rFFT along rows,
// keep k=0..4 as (re,im), scaled by 1/64.
// Output layout: (32, 16384, 8, 5, 2) float32, blocks row-major (hb*128+wb).
//
// CTA = 256 threads = 32 blocks (one hb, 32 consecutive wb) x 8 rows.
// Thread computes one 8-point rFFT in registers, stages 10 floats in smem,
// CTA flushes 10 KB contiguous output with coalesced float4 stores.

#define BH 1024
#define BW 1024

__global__ __launch_bounds__(256) void rfft8_kernel(
    const float* __restrict__ x, float* __restrict__ out)
{
    __shared__ float s[2560];  // 32 blocks * 80 floats = 10 KB

    const int t   = threadIdx.x;
    const int cta = blockIdx.x;
    const int wbg = cta & 3;            // which group of 32 wb (0..3)
    const int hb  = (cta >> 2) & 127;   // block-row (0..127)
    const int n   = cta >> 9;           // batch (0..31)

    const int wb_local = t >> 3;        // 0..31
    const int r        = t & 7;         // row within 8x8 block

    const int row = hb * 8 + r;
    const float* p = x + ((size_t)n * BH + row) * BW + (size_t)(wbg * 32 + wb_local) * 8;

    const float4 u = *reinterpret_cast<const float4*>(p);
    const float4 v = *reinterpret_cast<const float4*>(p + 4);

    // x0..x7 = u.x u.y u.z u.w v.x v.y v.z v.w
    const float a0 = u.x + v.x, a1 = u.x - v.x;   // x0 +- x4
    const float c0 = u.y + v.y, c1 = u.y - v.y;   // x1 +- x5
    const float b0 = u.z + v.z, b1 = u.z - v.z;   // x2 +- x6
    const float d0 = u.w + v.w, d1 = u.w - v.w;   // x3 +- x7

    const float C   = 0.70710678118654752440f;    // sqrt(2)/2
    const float e   = C * (c1 - d1);
    const float f   = C * (c1 + d1);
    const float inv = 1.0f / 64.0f;

    float* o = s + (wb_local * 8 + r) * 10;
    o[0] = (a0 + b0 + c0 + d0) * inv;  o[1] = 0.0f;              // X0
    o[2] = (a1 + e) * inv;             o[3] = (-b1 - f) * inv;   // X1
    o[4] = (a0 - b0) * inv;            o[5] = (d0 - c0) * inv;   // X2
    o[6] = (a1 - e) * inv;             o[7] = (b1 - f) * inv;    // X3
    o[8] = (a0 + b0 - c0 - d0) * inv;  o[9] = 0.0f;              // X4

    __syncthreads();

    // Flush 2560 floats = 640 float4, fully coalesced & contiguous in gmem.
    const size_t obase = ((size_t)n * 16384 + (size_t)hb * 128 + (size_t)wbg * 32) * 80;
    float4* og = reinterpret_cast<float4*>(out + obase);
    const float4* sg = reinterpret_cast<const float4*>(s);
    #pragma unroll
    for (int i = 0; i < 640; i += 256) {
        int idx = i + t;
        if (idx < 640) og[idx] = sg[idx];
    }
}

extern "C" void kernel_launch(void* const* d_in, const int* in_sizes, int n_in,
                              void* d_out, int out_size)
{
    const float* x = (const float*)d_in[0];
    float* out = (float*)d_out;
    // 32 batches * 128 hb * 4 wb-groups = 16384 CTAs, 256 threads each.
    rfft8_kernel<<<16384, 256>>>(x, out);
}

// round 3
// speedup vs baseline: 1.1965x; 1.1965x over previous
#include <cuda_runtime.h>
#include <cstdint>
#include <cstddef>

// RFFT2d: x (32,1,1024,1024) fp32 -> per 8x8 block, 8-point rFFT along rows,
// keep k=0..4 as (re,im), scaled by 1/64.
// Output layout: (32, 16384, 8, 5, 2) float32, blocks row-major (hb*128+wb).
//
// CTA = 256 threads = 32 blocks (one hb, 32 consecutive wb) x 8 rows.
// Thread computes one 8-point rFFT in registers, stages 10 floats in smem via
// conflict-free STS.64, then ONE bulk async copy (1-D, no tensormap) drains
// the 10 KB contiguous output tile smem -> gmem. fence.proxy.async orders the
// generic-proxy STS writes before the async-proxy bulk read (R2 bug fix).

#define BH 1024
#define BW 1024

__global__ __launch_bounds__(256) void rfft8_kernel(
    const float* __restrict__ x, float* __restrict__ out)
{
    __shared__ alignas(16) float s[2560];  // 32 blocks * 80 floats = 10 KB

    const int t   = threadIdx.x;
    const int cta = blockIdx.x;
    const int wbg = cta & 3;            // which group of 32 wb (0..3)
    const int hb  = (cta >> 2) & 127;   // block-row (0..127)
    const int n   = cta >> 9;           // batch (0..31)

    const int wb_local = t >> 3;        // 0..31
    const int r        = t & 7;         // row within 8x8 block

    const int row = hb * 8 + r;
    const float* p = x + ((size_t)n * BH + row) * BW + (size_t)(wbg * 32 + wb_local) * 8;

    const float4 u = *reinterpret_cast<const float4*>(p);
    const float4 v = *reinterpret_cast<const float4*>(p + 4);

    // x0..x7 = u.x u.y u.z u.w v.x v.y v.z v.w
    const float a0 = u.x + v.x, a1 = u.x - v.x;   // x0 +- x4
    const float c0 = u.y + v.y, c1 = u.y - v.y;   // x1 +- x5
    const float b0 = u.z + v.z, b1 = u.z - v.z;   // x2 +- x6
    const float d0 = u.w + v.w, d1 = u.w - v.w;   // x3 +- x7

    const float C   = 0.70710678118654752440f;    // sqrt(2)/2
    const float e   = C * (c1 - d1);
    const float f   = C * (c1 + d1);
    const float inv = 1.0f / 64.0f;

    // Conflict-free STS.64: word base 10*t, +2j; within each 16-lane phase the
    // 16 window starts are the 16 distinct even banks.
    float2* o = reinterpret_cast<float2*>(s + (wb_local * 8 + r) * 10);
    o[0] = make_float2((a0 + b0 + c0 + d0) * inv, 0.0f);               // X0
    o[1] = make_float2((a1 + e) * inv,            (-b1 - f) * inv);    // X1
    o[2] = make_float2((a0 - b0) * inv,           (d0 - c0) * inv);    // X2
    o[3] = make_float2((a1 - e) * inv,            (b1 - f) * inv);     // X3
    o[4] = make_float2((a0 + b0 - c0 - d0) * inv, 0.0f);               // X4

    __syncthreads();

    // Bulk async store: 10240 contiguous bytes smem -> gmem. The proxy fence
    // makes the barrier-ordered generic STS writes visible to the async proxy.
    if (t == 0) {
        asm volatile("fence.proxy.async.shared::cta;" ::: "memory");
        const size_t obase = (size_t)cta * 2560;   // floats
        float* g = out + obase;
        uint32_t saddr = (uint32_t)__cvta_generic_to_shared(s);
        asm volatile(
            "cp.async.bulk.global.shared::cta.bulk_group [%0], [%1], %2;"
            :: "l"(g), "r"(saddr), "n"(10240) : "memory");
        asm volatile("cp.async.bulk.commit_group;" ::: "memory");
        asm volatile("cp.async.bulk.wait_group 0;" ::: "memory");
    }
}

extern "C" void kernel_launch(void* const* d_in, const int* in_sizes, int n_in,
                              void* d_out, int out_size)
{
    const float* x = (const float*)d_in[0];
    float* out = (float*)d_out;
    // 32 batches * 128 hb * 4 wb-groups = 16384 CTAs, 256 threads each.
    rfft8_kernel<<<16384, 256>>>(x, out);
}

// round 4
// speedup vs baseline: 1.2912x; 1.0791x over previous
#include <cuda_runtime.h>
#include <cstdint>
#include <cstddef>

// RFFT2d: x (32,1,1024,1024) fp32 -> per 8x8 block, 8-point rFFT along rows,
// keep k=0..4 as (re,im), scaled by 1/64.
// Output layout: (32, 16384, 8, 5, 2) float32, blocks row-major (hb*128+wb).
//
// CTA = 256 threads = 32 blocks (one hb, 32 consecutive wb) x 8 rows.
// R4: line-dense LDG.128 (4 full cache lines per instr) + pair shfl.xor(1)
// to assemble each thread's 8-float block-row; STS.64 staging (2-way, same
// bank multiset as R3) and one proxy-fenced 10 KB bulk async store.

#define BW 1024

__global__ __launch_bounds__(256) void rfft8_kernel(
    const float* __restrict__ x, float* __restrict__ out)
{
    __shared__ alignas(16) float s[2560];  // 32 blocks * 80 floats = 10 KB

    const int t   = threadIdx.x;
    const int w   = t >> 5;             // warp 0..7
    const int l   = t & 31;             // lane
    const int cta = blockIdx.x;
    const int wbg = cta & 3;            // group of 32 wb (0..3)
    const int hb  = (cta >> 2) & 127;   // block-row (0..127)
    const int n   = cta >> 9;           // batch (0..31)

    // Dense loads: warp's tile = rows hb*8..+8, 128B-wide window (4 blocks).
    // LDG#0 covers rows 0..3 of the window densely, LDG#1 rows 4..7.
    const int r = l >> 3;               // 0..3
    const size_t base = ((size_t)(n * 1024 + hb * 8 + r)) * BW
                      + (size_t)(wbg * 32 + 4 * w) * 8 + 4 * (l & 7);
    const float4 A = *reinterpret_cast<const float4*>(x + base);            // row r
    const float4 B = *reinterpret_cast<const float4*>(x + base + 4 * BW);   // row r+4

    // Pair exchange: lanes l, l^1 hold the two halves (cols 0..3 / 4..7) of
    // block b'=(l>>1)&3, rows r and r+4. Even lane assembles row r, odd row r+4.
    const bool odd = (l & 1);
    const unsigned FULL = 0xffffffffu;
    float s0 = odd ? A.x : B.x;
    float s1 = odd ? A.y : B.y;
    float s2 = odd ? A.z : B.z;
    float s3 = odd ? A.w : B.w;
    float g0 = __shfl_xor_sync(FULL, s0, 1);
    float g1 = __shfl_xor_sync(FULL, s1, 1);
    float g2 = __shfl_xor_sync(FULL, s2, 1);
    float g3 = __shfl_xor_sync(FULL, s3, 1);

    const float x0 = odd ? g0 : A.x;
    const float x1 = odd ? g1 : A.y;
    const float x2 = odd ? g2 : A.z;
    const float x3 = odd ? g3 : A.w;
    const float x4 = odd ? B.x : g0;
    const float x5 = odd ? B.y : g1;
    const float x6 = odd ? B.z : g2;
    const float x7 = odd ? B.w : g3;

    // 8-point rFFT (split into even/odd radix-2 stages).
    const float a0 = x0 + x4, a1 = x0 - x4;
    const float c0 = x1 + x5, c1 = x1 - x5;
    const float b0 = x2 + x6, b1 = x2 - x6;
    const float d0 = x3 + x7, d1 = x3 - x7;

    const float C   = 0.70710678118654752440f;    // sqrt(2)/2
    const float e   = C * (c1 - d1);
    const float f   = C * (c1 + d1);
    const float inv = 1.0f / 64.0f;

    // Record owned by this thread: block wb_local = 4w + ((l>>1)&3),
    // row R = (l>>3) + 4*(l&1). rec = wb_local*8 + R = 32w + 8b' + 4p + r,
    // a permutation of lanes -> same 2-way STS bank multiset as R3.
    const int rec = 32 * w + 8 * ((l >> 1) & 3) + 4 * (l & 1) + (l >> 3);
    float2* o = reinterpret_cast<float2*>(s + rec * 10);
    o[0] = make_float2((a0 + b0 + c0 + d0) * inv, 0.0f);               // X0
    o[1] = make_float2((a1 + e) * inv,            (-b1 - f) * inv);    // X1
    o[2] = make_float2((a0 - b0) * inv,           (d0 - c0) * inv);    // X2
    o[3] = make_float2((a1 - e) * inv,            (b1 - f) * inv);     // X3
    o[4] = make_float2((a0 + b0 - c0 - d0) * inv, 0.0f);               // X4

    __syncthreads();

    // Bulk async store: 10240 contiguous bytes smem -> gmem; proxy fence
    // orders the barrier-ordered generic STS writes before the async proxy.
    if (t == 0) {
        asm volatile("fence.proxy.async.shared::cta;" ::: "memory");
        float* g = out + (size_t)cta * 2560;
        uint32_t saddr = (uint32_t)__cvta_generic_to_shared(s);
        asm volatile(
            "cp.async.bulk.global.shared::cta.bulk_group [%0], [%1], %2;"
            :: "l"(g), "r"(saddr), "n"(10240) : "memory");
        asm volatile("cp.async.bulk.commit_group;" ::: "memory");
        asm volatile("cp.async.bulk.wait_group 0;" ::: "memory");
    }
}

extern "C" void kernel_launch(void* const* d_in, const int* in_sizes, int n_in,
                              void* d_out, int out_size)
{
    const float* x = (const float*)d_in[0];
    float* out = (float*)d_out;
    // 32 batches * 128 hb * 4 wb-groups = 16384 CTAs, 256 threads each.
    rfft8_kernel<<<16384, 256>>>(x, out);
}